// round 13
// baseline (speedup 1.0000x reference)
#include <cuda_runtime.h>
#include <cstdint>
#include <cstddef>
#include <math.h>

#define H_DIM 256
#define MAXV 10000
#define MAXE 160000
#define LN_EPS 1e-5f
#define NTILE_MAX 640

__device__ float g_nodebuf[(size_t)MAXV * 1024];   // [ -- | Vh | Ah | Bh]
__device__ float g_agg[(size_t)MAXV * H_DIM];      // Uh+bias, then += gated agg
__device__ float g_ce[(size_t)MAXE * H_DIM];
__device__ float g_wtf[5 * 65536];                 // tf32 [Wu|Wv|Wa|Wb|Wc]
__device__ int   g_tile_ctr[2];                    // work-steal counters per half
__device__ int   g_done[NTILE_MAX];                // per-tile completion counters

__device__ __forceinline__ void red_add_v4(float* addr, float a, float b, float c, float d) {
    asm volatile("red.global.add.v4.f32 [%0], {%1,%2,%3,%4};"
                 :: "l"(addr), "f"(a), "f"(b), "f"(c), "f"(d));
}

__device__ __forceinline__ float to_tf32(float x) {
    float y;
    asm("cvt.rna.tf32.f32 %0, %1;" : "=f"(y) : "f"(x));
    return y;
}

__device__ __forceinline__ float4 tf32_4(float4 v) {
    return make_float4(to_tf32(v.x), to_tf32(v.y), to_tf32(v.z), to_tf32(v.w));
}

__device__ __forceinline__ void mma_tf32(float& d0, float& d1, float& d2, float& d3,
                                         float a0, float a1, float a2, float a3,
                                         float b0, float b1) {
    asm volatile(
        "mma.sync.aligned.m16n8k8.row.col.f32.tf32.tf32.f32 "
        "{%0,%1,%2,%3}, {%4,%5,%6,%7}, {%8,%9}, {%0,%1,%2,%3};\n"
        : "+f"(d0), "+f"(d1), "+f"(d2), "+f"(d3)
        : "r"(__float_as_uint(a0)), "r"(__float_as_uint(a1)),
          "r"(__float_as_uint(a2)), "r"(__float_as_uint(a3)),
          "r"(__float_as_uint(b0)), "r"(__float_as_uint(b1)));
}

__device__ __forceinline__ void cpa16(uint32_t saddr, const void* g) {
    asm volatile("cp.async.cg.shared.global [%0], [%1], 16;" :: "r"(saddr), "l"(g));
}
__device__ __forceinline__ void cpa_commit() {
    asm volatile("cp.async.commit_group;");
}
template <int N>
__device__ __forceinline__ void cpa_wait() {
    asm volatile("cp.async.wait_group %0;" :: "n"(N));
}

#define SA_STRIDE 36
#define SB_STRIDE 36
#define EB_STRIDE 260

// ---------------------------------------------------------------------------
// Kernel 0: init — tf32 weights, reset work-steal + done counters.
// ---------------------------------------------------------------------------
__global__ void init_kernel(
    const float* __restrict__ Wu, const float* __restrict__ Wv,
    const float* __restrict__ Wa, const float* __restrict__ Wb,
    const float* __restrict__ Wc)
{
    int i = blockIdx.x * blockDim.x + threadIdx.x;
    if (i < 2) g_tile_ctr[i] = 0;
    if (i < NTILE_MAX) g_done[i] = 0;
    int m = i >> 14;
    int r = i & 16383;
    const float* src = (m == 0) ? Wu : (m == 1) ? Wv : (m == 2) ? Wa : (m == 3) ? Wb : Wc;
    float4 v = __ldg(reinterpret_cast<const float4*>(src) + r);
    reinterpret_cast<float4*>(g_wtf)[i] = tf32_4(v);
}

// ---------------------------------------------------------------------------
// Kernel 1: node GEMM (2 CTAs/SM). by==0 writes Uh+bias into g_agg directly.
// ---------------------------------------------------------------------------
#define NG_SA0 0
#define NG_SA1 2304
#define NG_SB0 4608
#define NG_SB1 13824
#define NG_SMEM_BYTES 92160

__global__ __launch_bounds__(256, 2) void node_gemm_tc_kernel(
    const float* __restrict__ h,
    const float* __restrict__ bu, const float* __restrict__ bv,
    const float* __restrict__ ba, const float* __restrict__ bb,
    int V)
{
    extern __shared__ float smem[];
    const uint32_t smem_u32 = (uint32_t)__cvta_generic_to_shared(smem);

    const int by = blockIdx.y;
    const float* W = g_wtf + (size_t)by * 65536;
    const float* bias = (by == 0) ? bu : (by == 1) ? bv : (by == 2) ? ba : bb;

    const int tid  = threadIdx.x;
    const int w    = tid >> 5;
    const int lane = tid & 31;
    const int g    = lane >> 2;
    const int t    = lane & 3;
    const int row0 = blockIdx.x * 64;

    const int lr  = tid >> 2;
    const int lk8 = (tid & 3) * 8;

    int gr = row0 + lr; if (gr >= V) gr = V - 1;
    const float* arow = h + (size_t)gr * H_DIM + lk8;
    const float* brow = W + (size_t)tid * H_DIM;

    const uint32_t sa_a[2] = { smem_u32 + (NG_SA0 + lr * SA_STRIDE + lk8) * 4,
                               smem_u32 + (NG_SA1 + lr * SA_STRIDE + lk8) * 4 };
    const uint32_t sb_a[2] = { smem_u32 + (NG_SB0 + tid * SB_STRIDE) * 4,
                               smem_u32 + (NG_SB1 + tid * SB_STRIDE) * 4 };

    float acc[4][4][4];
    #pragma unroll
    for (int mt = 0; mt < 4; mt++)
        #pragma unroll
        for (int nt = 0; nt < 4; nt++)
            #pragma unroll
            for (int q = 0; q < 4; q++) acc[mt][nt][q] = 0.f;

    cpa16(sa_a[0],      arow);
    cpa16(sa_a[0] + 16, arow + 4);
    #pragma unroll
    for (int q = 0; q < 8; q++) cpa16(sb_a[0] + q * 16, brow + q * 4);
    cpa_commit();

    #pragma unroll
    for (int c = 0; c < 8; c++) {
        const int buf = c & 1;
        if (c < 7) {
            const int nbuf = buf ^ 1;
            const int kk = (c + 1) * 32;
            cpa16(sa_a[nbuf],      arow + kk);
            cpa16(sa_a[nbuf] + 16, arow + kk + 4);
            #pragma unroll
            for (int q = 0; q < 8; q++) cpa16(sb_a[nbuf] + q * 16, brow + kk + q * 4);
            cpa_commit();
            cpa_wait<1>();
        } else {
            cpa_wait<0>();
        }
        __syncthreads();

        const float* sA = smem + (buf ? NG_SA1 : NG_SA0);
        const float* sB = smem + (buf ? NG_SB1 : NG_SB0);
        #pragma unroll
        for (int ks = 0; ks < 4; ks++) {
            const int kb = ks * 8;
            float bf[4][2];
            #pragma unroll
            for (int nt = 0; nt < 4; nt++) {
                int n = w * 32 + nt * 8 + g;
                bf[nt][0] = sB[n * SB_STRIDE + kb + t];
                bf[nt][1] = sB[n * SB_STRIDE + kb + t + 4];
            }
            #pragma unroll
            for (int mt = 0; mt < 4; mt++) {
                int m = mt * 16;
                float a0 = sA[(m + g) * SA_STRIDE + kb + t];
                float a1 = sA[(m + g + 8) * SA_STRIDE + kb + t];
                float a2 = sA[(m + g) * SA_STRIDE + kb + t + 4];
                float a3 = sA[(m + g + 8) * SA_STRIDE + kb + t + 4];
                #pragma unroll
                for (int nt = 0; nt < 4; nt++)
                    mma_tf32(acc[mt][nt][0], acc[mt][nt][1], acc[mt][nt][2], acc[mt][nt][3],
                             a0, a1, a2, a3, bf[nt][0], bf[nt][1]);
            }
        }
        __syncthreads();
    }

    #pragma unroll
    for (int mt = 0; mt < 4; mt++) {
        #pragma unroll
        for (int nt = 0; nt < 4; nt++) {
            int cc = w * 32 + nt * 8 + 2 * t;
            int r0 = row0 + mt * 16 + g;
            int r1 = r0 + 8;
            if (r0 < V) {
                float* o = (by == 0) ? (g_agg + (size_t)r0 * H_DIM + cc)
                                     : (g_nodebuf + (size_t)r0 * 1024 + by * 256 + cc);
                o[0] = acc[mt][nt][0] + bias[cc];
                o[1] = acc[mt][nt][1] + bias[cc + 1];
            }
            if (r1 < V) {
                float* o = (by == 0) ? (g_agg + (size_t)r1 * H_DIM + cc)
                                     : (g_nodebuf + (size_t)r1 * 1024 + by * 256 + cc);
                o[0] = acc[mt][nt][2] + bias[cc];
                o[1] = acc[mt][nt][3] + bias[cc + 1];
            }
        }
    }
}

// ---------------------------------------------------------------------------
// Kernel 2: merged persistent edge GEMM + epilogue.
// grid (2, 74). Each block: persistent 128-col Wc half, work-steals 256-edge
// tiles. After storing its Ce half (normal policy -> L2-resident), it bumps
// g_done[tile]; the SECOND arriver runs the full 256-col epilogue for the
// tile (gather/gate/atomic/LN/residual) while Ce and e are still L2-hot.
// ---------------------------------------------------------------------------
#define EG_B_OFF 0
#define EG_A_OFF 33280
#define EG_A_BUF 9216
#define EG_SMEM_BYTES 206848

__global__ __launch_bounds__(512, 1) void edge_fused_persistent(
    const float* __restrict__ e,
    const int*   __restrict__ ei,
    const float* __restrict__ bc,
    const float* __restrict__ ge, const float* __restrict__ be,
    float* __restrict__ e_out,
    int E)
{
    extern __shared__ float smem[];
    const uint32_t smem_u32 = (uint32_t)__cvta_generic_to_shared(smem);
    __shared__ int s_tile, s_done;
    __shared__ int sSrc[256], sDst[256];
    __shared__ float sBc[256], sGe[256], sBe[256];

    const int nb = blockIdx.x;                 // 128-col half of Wc
    const int tid  = threadIdx.x;
    const int w    = tid >> 5;
    const int lane = tid & 31;
    const int g    = lane >> 2;
    const int t    = lane & 3;
    const int wm   = w >> 1;
    const int wn   = w & 1;

    const int ar0 = tid >> 3;
    const int aq  = (tid & 7) * 4;

    const int nTiles = E / 256;

    if (tid < 256) { sBc[tid] = bc[tid]; sGe[tid] = ge[tid]; sBe[tid] = be[tid]; }

    // persistent B half
    {
        const float* Wcv = g_wtf + 4 * 65536 + (size_t)(nb * 128) * H_DIM;
        #pragma unroll
        for (int i = 0; i < 16; i++) {
            int fi = tid + i * 512;
            int n  = fi >> 6;
            int q  = fi & 63;
            cpa16(smem_u32 + (EG_B_OFF + n * EB_STRIDE + q * 4) * 4,
                  Wcv + (size_t)n * H_DIM + q * 4);
        }
        cpa_commit();
    }

    const uint32_t sa_base[2] = {
        smem_u32 + (EG_A_OFF + 0 * EG_A_BUF + ar0 * SA_STRIDE + aq) * 4,
        smem_u32 + (EG_A_OFF + 1 * EG_A_BUF + ar0 * SA_STRIDE + aq) * 4 };
    const float* sB = smem + EG_B_OFF;

    while (true) {
        if (tid == 0) s_tile = atomicAdd(&g_tile_ctr[nb], 1);
        __syncthreads();
        const int ti = s_tile;
        if (ti >= nTiles) break;

        const int e0 = ti * 256;
        const float* abase = e + (size_t)(e0 + ar0) * H_DIM + aq;

        float acc[2][8][4];
        #pragma unroll
        for (int mt = 0; mt < 2; mt++)
            #pragma unroll
            for (int nt = 0; nt < 8; nt++)
                #pragma unroll
                for (int q = 0; q < 4; q++) acc[mt][nt][q] = 0.f;

        #pragma unroll
        for (int i = 0; i < 4; i++)
            cpa16(sa_base[0] + i * 64 * SA_STRIDE * 4, abase + (size_t)i * 64 * H_DIM);
        cpa_commit();

        #pragma unroll
        for (int c = 0; c < 8; c++) {
            if (c < 7) {
                const int nbuf = (c + 1) & 1;
                const int kk = (c + 1) * 32;
                #pragma unroll
                for (int i = 0; i < 4; i++)
                    cpa16(sa_base[nbuf] + i * 64 * SA_STRIDE * 4,
                          abase + (size_t)i * 64 * H_DIM + kk);
                cpa_commit();
                cpa_wait<1>();
            } else {
                cpa_wait<0>();
            }
            __syncthreads();

            const float* sA = smem + EG_A_OFF + (c & 1) * EG_A_BUF;
            const int kg = c * 32;
            #pragma unroll
            for (int ks = 0; ks < 4; ks++) {
                const int kb = ks * 8;
                float bf[8][2];
                #pragma unroll
                for (int nt = 0; nt < 8; nt++) {
                    int n = wn * 64 + nt * 8 + g;
                    bf[nt][0] = sB[n * EB_STRIDE + kg + kb + t];
                    bf[nt][1] = sB[n * EB_STRIDE + kg + kb + t + 4];
                }
                #pragma unroll
                for (int mt = 0; mt < 2; mt++) {
                    int m = wm * 32 + mt * 16;
                    float a0 = sA[(m + g) * SA_STRIDE + kb + t];
                    float a1 = sA[(m + g + 8) * SA_STRIDE + kb + t];
                    float a2 = sA[(m + g) * SA_STRIDE + kb + t + 4];
                    float a3 = sA[(m + g + 8) * SA_STRIDE + kb + t + 4];
                    #pragma unroll
                    for (int nt = 0; nt < 8; nt++)
                        mma_tf32(acc[mt][nt][0], acc[mt][nt][1], acc[mt][nt][2], acc[mt][nt][3],
                                 a0, a1, a2, a3, bf[nt][0], bf[nt][1]);
                }
            }
            __syncthreads();
        }

        // store Ce half — NORMAL policy so it stays L2-resident for the consumer
        #pragma unroll
        for (int mt = 0; mt < 2; mt++) {
            #pragma unroll
            for (int nt = 0; nt < 8; nt++) {
                int col = nb * 128 + wn * 64 + nt * 8 + 2 * t;
                int r0 = wm * 32 + mt * 16 + g;
                float* o0 = g_ce + (size_t)(e0 + r0) * H_DIM + col;
                float* o1 = g_ce + (size_t)(e0 + r0 + 8) * H_DIM + col;
                *reinterpret_cast<float2*>(o0) = make_float2(acc[mt][nt][0], acc[mt][nt][1]);
                *reinterpret_cast<float2*>(o1) = make_float2(acc[mt][nt][2], acc[mt][nt][3]);
            }
        }

        // release: make Ce visible, then bump the tile counter
        __threadfence();
        __syncthreads();
        if (tid == 0) s_done = atomicAdd(&g_done[ti], 1);
        __syncthreads();

        if (s_done == 1) {
            // second arriver: both halves of Ce are in L2 — run the epilogue
            __threadfence();   // acquire
            if (tid < 256) {
                sSrc[tid] = __ldg(ei + e0 + tid);
                sDst[tid] = __ldg(ei + E + e0 + tid);
            }
            __syncthreads();

            const int col0 = lane * 8;
            #pragma unroll 4
            for (int k = 0; k < 16; k++) {
                const int row = w * 16 + k;
                const int er  = e0 + row;
                const int s = sSrc[row];
                const int d = sDst[row];

                const float4* cep = reinterpret_cast<const float4*>(g_ce + (size_t)er * H_DIM + col0);
                const float4* ah  = reinterpret_cast<const float4*>(g_nodebuf + (size_t)d * 1024 + 512 + col0);
                const float4* bh  = reinterpret_cast<const float4*>(g_nodebuf + (size_t)s * 1024 + 768 + col0);
                const float4* vh  = reinterpret_cast<const float4*>(g_nodebuf + (size_t)d * 1024 + 256 + col0);
                const float4* erp = reinterpret_cast<const float4*>(e + (size_t)er * H_DIM + col0);

                float4 c0 = __ldg(cep), c1 = __ldg(cep + 1);
                float4 a0 = __ldg(ah),  a1 = __ldg(ah + 1);
                float4 b0 = __ldg(bh),  b1 = __ldg(bh + 1);
                float4 v0 = __ldg(vh),  v1 = __ldg(vh + 1);
                float4 r0 = __ldg(erp), r1 = __ldg(erp + 1);

                float x[8], vhv[8], erv[8];
                x[0] = c0.x + a0.x + b0.x; x[1] = c0.y + a0.y + b0.y;
                x[2] = c0.z + a0.z + b0.z; x[3] = c0.w + a0.w + b0.w;
                x[4] = c1.x + a1.x + b1.x; x[5] = c1.y + a1.y + b1.y;
                x[6] = c1.z + a1.z + b1.z; x[7] = c1.w + a1.w + b1.w;
                vhv[0] = v0.x; vhv[1] = v0.y; vhv[2] = v0.z; vhv[3] = v0.w;
                vhv[4] = v1.x; vhv[5] = v1.y; vhv[6] = v1.z; vhv[7] = v1.w;
                erv[0] = r0.x; erv[1] = r0.y; erv[2] = r0.z; erv[3] = r0.w;
                erv[4] = r1.x; erv[5] = r1.y; erv[6] = r1.z; erv[7] = r1.w;

                float sum = 0.f, sq = 0.f;
                #pragma unroll
                for (int cc = 0; cc < 8; cc++) {
                    float xv = x[cc] + sBc[col0 + cc];
                    x[cc] = xv;
                    sum += xv;
                    sq  += xv * xv;
                }

                float gv[8];
                #pragma unroll
                for (int cc = 0; cc < 8; cc++) {
                    float gt = 1.f / (1.f + __expf(-x[cc]));
                    gv[cc] = gt * vhv[cc];
                }
                float* ag = g_agg + (size_t)s * H_DIM + col0;
                red_add_v4(ag,     gv[0], gv[1], gv[2], gv[3]);
                red_add_v4(ag + 4, gv[4], gv[5], gv[6], gv[7]);

                #pragma unroll
                for (int off = 16; off > 0; off >>= 1) {
                    sum += __shfl_xor_sync(0xFFFFFFFFu, sum, off);
                    sq  += __shfl_xor_sync(0xFFFFFFFFu, sq,  off);
                }
                const float mu  = sum * (1.f / 256.f);
                const float var = sq * (1.f / 256.f) - mu * mu;
                const float rs  = rsqrtf(var + LN_EPS);

                float4 o0, o1;
                float* ov0 = &o0.x; float* ov1 = &o1.x;
                #pragma unroll
                for (int cc = 0; cc < 4; cc++) {
                    float y = (x[cc] - mu) * rs * sGe[col0 + cc] + sBe[col0 + cc];
                    y = y > 0.f ? y : 0.f;
                    ov0[cc] = erv[cc] + y;
                }
                #pragma unroll
                for (int cc = 0; cc < 4; cc++) {
                    float y = (x[cc + 4] - mu) * rs * sGe[col0 + cc + 4] + sBe[col0 + cc + 4];
                    y = y > 0.f ? y : 0.f;
                    ov1[cc] = erv[cc + 4] + y;
                }
                float4* orow = reinterpret_cast<float4*>(e_out + (size_t)er * H_DIM + col0);
                __stcs(orow, o0);
                __stcs(orow + 1, o1);
            }
            __syncthreads();
        }
    }
}

// ---------------------------------------------------------------------------
// Kernel 3: node epilogue — g_agg already holds Uh + bias + agg.
// ---------------------------------------------------------------------------
__global__ __launch_bounds__(256) void node_epilogue_kernel(
    const float* __restrict__ h,
    const float* __restrict__ gh, const float* __restrict__ bhv,
    float* __restrict__ h_out, int V)
{
    const int warp = threadIdx.x >> 5;
    const int lane = threadIdx.x & 31;
    const int n = blockIdx.x * 8 + warp;
    if (n >= V) return;
    const int col0 = lane * 8;

    const float4* ag = reinterpret_cast<const float4*>(g_agg + (size_t)n * H_DIM + col0);
    const float4* hr = reinterpret_cast<const float4*>(h     + (size_t)n * H_DIM + col0);

    float4 g0 = __ldcs(ag), g1 = __ldcs(ag + 1);
    float4 h0 = __ldcs(hr), h1 = __ldcs(hr + 1);

    float x[8], hv[8];
    x[0] = g0.x; x[1] = g0.y; x[2] = g0.z; x[3] = g0.w;
    x[4] = g1.x; x[5] = g1.y; x[6] = g1.z; x[7] = g1.w;
    hv[0] = h0.x; hv[1] = h0.y; hv[2] = h0.z; hv[3] = h0.w;
    hv[4] = h1.x; hv[5] = h1.y; hv[6] = h1.z; hv[7] = h1.w;

    float sum = 0.f, sq = 0.f;
    #pragma unroll
    for (int c = 0; c < 8; c++) { sum += x[c]; sq += x[c] * x[c]; }
    #pragma unroll
    for (int off = 16; off > 0; off >>= 1) {
        sum += __shfl_xor_sync(0xFFFFFFFFu, sum, off);
        sq  += __shfl_xor_sync(0xFFFFFFFFu, sq,  off);
    }
    const float mu  = sum * (1.f / 256.f);
    const float var = sq * (1.f / 256.f) - mu * mu;
    const float rs  = rsqrtf(var + LN_EPS);

    float4 o0, o1;
    float* ov0 = &o0.x; float* ov1 = &o1.x;
    #pragma unroll
    for (int c = 0; c < 4; c++) {
        float y = (x[c] - mu) * rs * gh[col0 + c] + bhv[col0 + c];
        y = y > 0.f ? y : 0.f;
        ov0[c] = hv[c] + y;
    }
    #pragma unroll
    for (int c = 0; c < 4; c++) {
        float y = (x[c + 4] - mu) * rs * gh[col0 + c + 4] + bhv[col0 + c + 4];
        y = y > 0.f ? y : 0.f;
        ov1[c] = hv[c + 4] + y;
    }
    float4* o = reinterpret_cast<float4*>(h_out + (size_t)n * H_DIM + col0);
    __stcs(o, o0);
    __stcs(o + 1, o1);
}

// ---------------------------------------------------------------------------
extern "C" void kernel_launch(void* const* d_in, const int* in_sizes, int n_in,
                              void* d_out, int out_size)
{
    const float* h  = (const float*)d_in[0];
    const float* e  = (const float*)d_in[1];
    const int*   ei = (const int*)  d_in[2];
    const float* Wu = (const float*)d_in[3];
    const float* bu = (const float*)d_in[4];
    const float* Wv = (const float*)d_in[5];
    const float* bv = (const float*)d_in[6];
    const float* Wa = (const float*)d_in[7];
    const float* ba = (const float*)d_in[8];
    const float* Wb = (const float*)d_in[9];
    const float* bb = (const float*)d_in[10];
    const float* Wc = (const float*)d_in[11];
    const float* bc = (const float*)d_in[12];
    const float* gh = (const float*)d_in[13];
    const float* bh = (const float*)d_in[14];
    const float* ge = (const float*)d_in[15];
    const float* be = (const float*)d_in[16];

    const int V = in_sizes[0] / H_DIM;
    const int E = in_sizes[1] / H_DIM;

    float* h_out = (float*)d_out;
    float* e_out = (float*)d_out + (size_t)V * H_DIM;

    static int attr_set = 0;
    if (!attr_set) {
        cudaFuncSetAttribute(node_gemm_tc_kernel,
                             cudaFuncAttributeMaxDynamicSharedMemorySize, NG_SMEM_BYTES);
        cudaFuncSetAttribute(edge_fused_persistent,
                             cudaFuncAttributeMaxDynamicSharedMemorySize, EG_SMEM_BYTES);
        attr_set = 1;
    }

    init_kernel<<<320, 256>>>(Wu, Wv, Wa, Wb, Wc);

    dim3 g1((V + 63) / 64, 4);
    node_gemm_tc_kernel<<<g1, 256, NG_SMEM_BYTES>>>(h, bu, bv, ba, bb, V);

    dim3 g2(2, 74);   // persistent merged GEMM + epilogue
    edge_fused_persistent<<<g2, 512, EG_SMEM_BYTES>>>(e, ei, bc, ge, be, e_out, E);

    node_epilogue_kernel<<<(V + 7) / 8, 256>>>(h, gh, bh, h_out, V);
}

// round 14
// speedup vs baseline: 1.6305x; 1.6305x over previous
#include <cuda_runtime.h>
#include <cstdint>
#include <cstddef>
#include <math.h>

#define H_DIM 256
#define MAXV 10000
#define MAXE 160000
#define LN_EPS 1e-5f

__device__ float g_nodebuf[(size_t)MAXV * 1024];   // [ -- | Vh | Ah | Bh]
__device__ float g_agg[(size_t)MAXV * H_DIM];      // Uh+bias, then += gated agg
__device__ float g_ce[(size_t)MAXE * H_DIM];
__device__ float g_wtf[5 * 65536];                 // tf32 [Wu|Wv|Wa|Wb|Wc]
__device__ int   g_tile_ctr[16];                   // [0..1]=edge halves, [2..9]=node groups

__device__ __forceinline__ void red_add_v4(float* addr, float a, float b, float c, float d) {
    asm volatile("red.global.add.v4.f32 [%0], {%1,%2,%3,%4};"
                 :: "l"(addr), "f"(a), "f"(b), "f"(c), "f"(d));
}

__device__ __forceinline__ float to_tf32(float x) {
    float y;
    asm("cvt.rna.tf32.f32 %0, %1;" : "=f"(y) : "f"(x));
    return y;
}

__device__ __forceinline__ float4 tf32_4(float4 v) {
    return make_float4(to_tf32(v.x), to_tf32(v.y), to_tf32(v.z), to_tf32(v.w));
}

__device__ __forceinline__ void mma_tf32(float& d0, float& d1, float& d2, float& d3,
                                         float a0, float a1, float a2, float a3,
                                         float b0, float b1) {
    asm volatile(
        "mma.sync.aligned.m16n8k8.row.col.f32.tf32.tf32.f32 "
        "{%0,%1,%2,%3}, {%4,%5,%6,%7}, {%8,%9}, {%0,%1,%2,%3};\n"
        : "+f"(d0), "+f"(d1), "+f"(d2), "+f"(d3)
        : "r"(__float_as_uint(a0)), "r"(__float_as_uint(a1)),
          "r"(__float_as_uint(a2)), "r"(__float_as_uint(a3)),
          "r"(__float_as_uint(b0)), "r"(__float_as_uint(b1)));
}

__device__ __forceinline__ void cpa16(uint32_t saddr, const void* g) {
    asm volatile("cp.async.cg.shared.global [%0], [%1], 16;" :: "r"(saddr), "l"(g));
}
__device__ __forceinline__ void cpa_commit() {
    asm volatile("cp.async.commit_group;");
}
template <int N>
__device__ __forceinline__ void cpa_wait() {
    asm volatile("cp.async.wait_group %0;" :: "n"(N));
}

#define SA_STRIDE 36    // fragment bank = (4g+t+kb)%32: conflict-free permutation
#define EB_STRIDE 260   // persistent B rows: 260%32=4 -> same permutation

// Shared persistent-GEMM smem layout (both GEMM kernels):
// B[128*260=33280] + A double buffer[2 * 256*36=9216] = 51712 floats = 206848 B
#define PG_B_OFF 0
#define PG_A_OFF 33280
#define PG_A_BUF 9216
#define PG_SMEM_BYTES 206848

// ---------------------------------------------------------------------------
// Kernel 0: init — tf32 weights + reset work-steal counters.
// ---------------------------------------------------------------------------
__global__ void init_kernel(
    const float* __restrict__ Wu, const float* __restrict__ Wv,
    const float* __restrict__ Wa, const float* __restrict__ Wb,
    const float* __restrict__ Wc)
{
    int i = blockIdx.x * blockDim.x + threadIdx.x;
    if (i < 16) g_tile_ctr[i] = 0;
    int m = i >> 14;
    int r = i & 16383;
    const float* src = (m == 0) ? Wu : (m == 1) ? Wv : (m == 2) ? Wa : (m == 3) ? Wb : Wc;
    float4 v = __ldg(reinterpret_cast<const float4*>(src) + r);
    reinterpret_cast<float4*>(g_wtf)[i] = tf32_4(v);
}

// ---------------------------------------------------------------------------
// Generic persistent 256x128 GEMM mainloop body (A from `src`, B resident).
// Used by both node and edge GEMMs; tile row base = r0base, rows clamped to V.
// ---------------------------------------------------------------------------
struct TileAcc { float a[2][8][4]; };

__device__ __forceinline__ void pg_mainloop(
    const float* __restrict__ src, int r0base, int rowClamp,
    const float* sB_sm, float* smem, const uint32_t* sa_base,
    int ar0, int wm, int wn, int g, int t, TileAcc& A)
{
    #pragma unroll
    for (int mt = 0; mt < 2; mt++)
        #pragma unroll
        for (int nt = 0; nt < 8; nt++)
            #pragma unroll
            for (int q = 0; q < 4; q++) A.a[mt][nt][q] = 0.f;

    const int aq = 0; (void)aq;
    // prologue: chunk 0 -> buf 0 (4 rows per thread, clamped)
    #pragma unroll
    for (int i = 0; i < 4; i++) {
        int rr = r0base + ar0 + i * 64; if (rr > rowClamp) rr = rowClamp;
        cpa16(sa_base[0] + i * 64 * SA_STRIDE * 4, src + (size_t)rr * H_DIM);
    }
    cpa_commit();

    #pragma unroll
    for (int c = 0; c < 8; c++) {
        if (c < 7) {
            const int nbuf = (c + 1) & 1;
            const int kk = (c + 1) * 32;
            #pragma unroll
            for (int i = 0; i < 4; i++) {
                int rr = r0base + ar0 + i * 64; if (rr > rowClamp) rr = rowClamp;
                cpa16(sa_base[nbuf] + i * 64 * SA_STRIDE * 4, src + (size_t)rr * H_DIM + kk);
            }
            cpa_commit();
            cpa_wait<1>();
        } else {
            cpa_wait<0>();
        }
        __syncthreads();

        const float* sA = smem + PG_A_OFF + (c & 1) * PG_A_BUF;
        const int kg = c * 32;
        #pragma unroll
        for (int ks = 0; ks < 4; ks++) {
            const int kb = ks * 8;
            float bf[8][2];
            #pragma unroll
            for (int nt = 0; nt < 8; nt++) {
                int n = wn * 64 + nt * 8 + g;
                bf[nt][0] = sB_sm[n * EB_STRIDE + kg + kb + t];
                bf[nt][1] = sB_sm[n * EB_STRIDE + kg + kb + t + 4];
            }
            #pragma unroll
            for (int mt = 0; mt < 2; mt++) {
                int m = wm * 32 + mt * 16;
                float a0 = sA[(m + g) * SA_STRIDE + kb + t];
                float a1 = sA[(m + g + 8) * SA_STRIDE + kb + t];
                float a2 = sA[(m + g) * SA_STRIDE + kb + t + 4];
                float a3 = sA[(m + g + 8) * SA_STRIDE + kb + t + 4];
                #pragma unroll
                for (int nt = 0; nt < 8; nt++)
                    mma_tf32(A.a[mt][nt][0], A.a[mt][nt][1], A.a[mt][nt][2], A.a[mt][nt][3],
                             a0, a1, a2, a3, bf[nt][0], bf[nt][1]);
            }
        }
        __syncthreads();
    }
}

__device__ __forceinline__ void pg_load_B(const float* Wrows, uint32_t smem_u32, int tid) {
    #pragma unroll
    for (int i = 0; i < 16; i++) {
        int fi = tid + i * 512;
        int n  = fi >> 6;
        int q  = fi & 63;
        cpa16(smem_u32 + (PG_B_OFF + n * EB_STRIDE + q * 4) * 4,
              Wrows + (size_t)n * H_DIM + q * 4);
    }
    cpa_commit();
}

// ---------------------------------------------------------------------------
// Kernel 1: persistent node GEMM. grid (8, 18): blockIdx.x = column group
// (matrix m = gidx>>1, 128-col half = gidx&1). Work-steals 256-row tiles.
// Uh group (m==0) writes into g_agg (replaces zero_agg).
// ---------------------------------------------------------------------------
__global__ __launch_bounds__(512, 1) void node_gemm_persistent(
    const float* __restrict__ h,
    const float* __restrict__ bu, const float* __restrict__ bv,
    const float* __restrict__ ba, const float* __restrict__ bb,
    int V)
{
    extern __shared__ float smem[];
    const uint32_t smem_u32 = (uint32_t)__cvta_generic_to_shared(smem);
    __shared__ int s_tile;

    const int gidx = blockIdx.x;     // 0..7
    const int m    = gidx >> 1;      // matrix
    const int ch   = gidx & 1;       // col half
    const float* bias = (m == 0) ? bu : (m == 1) ? bv : (m == 2) ? ba : bb;

    const int tid  = threadIdx.x;
    const int w    = tid >> 5;
    const int lane = tid & 31;
    const int g    = lane >> 2;
    const int t    = lane & 3;
    const int wm   = w >> 1;
    const int wn   = w & 1;
    const int ar0  = tid >> 3;
    const int aq   = (tid & 7) * 4;

    const int nTiles = (V + 255) / 256;

    pg_load_B(g_wtf + (size_t)m * 65536 + (size_t)(ch * 128) * H_DIM, smem_u32, tid);

    const uint32_t sa_base[2] = {
        smem_u32 + (PG_A_OFF + 0 * PG_A_BUF + ar0 * SA_STRIDE + aq) * 4,
        smem_u32 + (PG_A_OFF + 1 * PG_A_BUF + ar0 * SA_STRIDE + aq) * 4 };
    const float* sB = smem + PG_B_OFF;
    const float* hsrc = h + aq;

    while (true) {
        if (tid == 0) s_tile = atomicAdd(&g_tile_ctr[2 + gidx], 1);
        __syncthreads();
        const int ti = s_tile;
        if (ti >= nTiles) break;

        const int r0base = ti * 256;
        TileAcc A;
        pg_mainloop(hsrc, r0base, V - 1, sB, smem, sa_base, ar0, wm, wn, g, t, A);

        #pragma unroll
        for (int mt = 0; mt < 2; mt++) {
            #pragma unroll
            for (int nt = 0; nt < 8; nt++) {
                int col = ch * 128 + wn * 64 + nt * 8 + 2 * t;  // 0..255 within matrix m
                int r0 = r0base + wm * 32 + mt * 16 + g;
                float b0v = bias[col], b1v = bias[col + 1];
                if (r0 < V) {
                    float* o = (m == 0) ? (g_agg + (size_t)r0 * H_DIM + col)
                                        : (g_nodebuf + (size_t)r0 * 1024 + m * 256 + col);
                    o[0] = A.a[mt][nt][0] + b0v;
                    o[1] = A.a[mt][nt][1] + b1v;
                }
                if (r0 + 8 < V) {
                    float* o = (m == 0) ? (g_agg + (size_t)(r0 + 8) * H_DIM + col)
                                        : (g_nodebuf + (size_t)(r0 + 8) * 1024 + m * 256 + col);
                    o[0] = A.a[mt][nt][2] + b0v;
                    o[1] = A.a[mt][nt][3] + b1v;
                }
            }
        }
    }
}

// ---------------------------------------------------------------------------
// Kernel 2a: persistent edge GEMM (R12-validated). grid (2, 74).
// ---------------------------------------------------------------------------
__global__ __launch_bounds__(512, 1) void edge_gemm_kernel(
    const float* __restrict__ e, int E)
{
    extern __shared__ float smem[];
    const uint32_t smem_u32 = (uint32_t)__cvta_generic_to_shared(smem);
    __shared__ int s_tile;

    const int nb = blockIdx.x;
    const int tid  = threadIdx.x;
    const int w    = tid >> 5;
    const int lane = tid & 31;
    const int g    = lane >> 2;
    const int t    = lane & 3;
    const int wm   = w >> 1;
    const int wn   = w & 1;
    const int ar0  = tid >> 3;
    const int aq   = (tid & 7) * 4;

    const int nTiles = E / 256;

    pg_load_B(g_wtf + 4 * 65536 + (size_t)(nb * 128) * H_DIM, smem_u32, tid);

    const uint32_t sa_base[2] = {
        smem_u32 + (PG_A_OFF + 0 * PG_A_BUF + ar0 * SA_STRIDE + aq) * 4,
        smem_u32 + (PG_A_OFF + 1 * PG_A_BUF + ar0 * SA_STRIDE + aq) * 4 };
    const float* sB = smem + PG_B_OFF;
    const float* esrc = e + aq;

    while (true) {
        if (tid == 0) s_tile = atomicAdd(&g_tile_ctr[nb], 1);
        __syncthreads();
        const int ti = s_tile;
        if (ti >= nTiles) break;

        const int e0 = ti * 256;
        TileAcc A;
        pg_mainloop(esrc, e0, E - 1, sB, smem, sa_base, ar0, wm, wn, g, t, A);

        #pragma unroll
        for (int mt = 0; mt < 2; mt++) {
            #pragma unroll
            for (int nt = 0; nt < 8; nt++) {
                int col = nb * 128 + wn * 64 + nt * 8 + 2 * t;
                int r0 = wm * 32 + mt * 16 + g;
                float* o0 = g_ce + (size_t)(e0 + r0) * H_DIM + col;
                float* o1 = g_ce + (size_t)(e0 + r0 + 8) * H_DIM + col;
                __stcs(reinterpret_cast<float2*>(o0), make_float2(A.a[mt][nt][0], A.a[mt][nt][1]));
                __stcs(reinterpret_cast<float2*>(o1), make_float2(A.a[mt][nt][2], A.a[mt][nt][3]));
            }
        }
    }
}

// ---------------------------------------------------------------------------
// Kernel 2b: edge epilogue (R12-validated: warp per edge)
// ---------------------------------------------------------------------------
__global__ __launch_bounds__(256) void edge_epilogue_kernel(
    const float* __restrict__ e,
    const int*   __restrict__ ei,
    const float* __restrict__ bc,
    const float* __restrict__ ge, const float* __restrict__ be,
    float* __restrict__ e_out,
    int E)
{
    __shared__ float sBc[256], sGe[256], sBe[256];
    const int tid = threadIdx.x;
    sBc[tid] = bc[tid]; sGe[tid] = ge[tid]; sBe[tid] = be[tid];
    __syncthreads();

    const int warp = tid >> 5;
    const int lane = tid & 31;
    const int col0 = lane * 8;
    const int er = blockIdx.x * 8 + warp;

    const int s = __ldg(ei + er);
    const int d = __ldg(ei + E + er);

    const float4* cep = reinterpret_cast<const float4*>(g_ce + (size_t)er * H_DIM + col0);
    const float4* ah = reinterpret_cast<const float4*>(g_nodebuf + (size_t)d * 1024 + 512 + col0);
    const float4* bh = reinterpret_cast<const float4*>(g_nodebuf + (size_t)s * 1024 + 768 + col0);
    const float4* vh = reinterpret_cast<const float4*>(g_nodebuf + (size_t)d * 1024 + 256 + col0);
    const float4* erp = reinterpret_cast<const float4*>(e + (size_t)er * H_DIM + col0);

    float4 c0 = __ldcs(cep), c1 = __ldcs(cep + 1);
    float4 a0 = __ldg(ah),   a1 = __ldg(ah + 1);
    float4 b0 = __ldg(bh),   b1 = __ldg(bh + 1);
    float4 v0 = __ldg(vh),   v1 = __ldg(vh + 1);
    float4 r0 = __ldcs(erp), r1 = __ldcs(erp + 1);

    float x[8], vhv[8], erv[8];
    x[0] = c0.x + a0.x + b0.x; x[1] = c0.y + a0.y + b0.y;
    x[2] = c0.z + a0.z + b0.z; x[3] = c0.w + a0.w + b0.w;
    x[4] = c1.x + a1.x + b1.x; x[5] = c1.y + a1.y + b1.y;
    x[6] = c1.z + a1.z + b1.z; x[7] = c1.w + a1.w + b1.w;
    vhv[0] = v0.x; vhv[1] = v0.y; vhv[2] = v0.z; vhv[3] = v0.w;
    vhv[4] = v1.x; vhv[5] = v1.y; vhv[6] = v1.z; vhv[7] = v1.w;
    erv[0] = r0.x; erv[1] = r0.y; erv[2] = r0.z; erv[3] = r0.w;
    erv[4] = r1.x; erv[5] = r1.y; erv[6] = r1.z; erv[7] = r1.w;

    float sum = 0.f, sq = 0.f;
    #pragma unroll
    for (int c = 0; c < 8; c++) {
        float xv = x[c] + sBc[col0 + c];
        x[c] = xv;
        sum += xv;
        sq  += xv * xv;
    }

    float gv[8];
    #pragma unroll
    for (int c = 0; c < 8; c++) {
        float gt = 1.f / (1.f + __expf(-x[c]));
        gv[c] = gt * vhv[c];
    }
    float* ag = g_agg + (size_t)s * H_DIM + col0;
    red_add_v4(ag,     gv[0], gv[1], gv[2], gv[3]);
    red_add_v4(ag + 4, gv[4], gv[5], gv[6], gv[7]);

    #pragma unroll
    for (int off = 16; off > 0; off >>= 1) {
        sum += __shfl_xor_sync(0xFFFFFFFFu, sum, off);
        sq  += __shfl_xor_sync(0xFFFFFFFFu, sq,  off);
    }
    const float mu  = sum * (1.f / 256.f);
    const float var = sq * (1.f / 256.f) - mu * mu;
    const float rs  = rsqrtf(var + LN_EPS);

    float4 o0, o1;
    float* ov0 = &o0.x; float* ov1 = &o1.x;
    #pragma unroll
    for (int c = 0; c < 4; c++) {
        float y = (x[c] - mu) * rs * sGe[col0 + c] + sBe[col0 + c];
        y = y > 0.f ? y : 0.f;
        ov0[c] = erv[c] + y;
    }
    #pragma unroll
    for (int c = 0; c < 4; c++) {
        float y = (x[c + 4] - mu) * rs * sGe[col0 + c + 4] + sBe[col0 + c + 4];
        y = y > 0.f ? y : 0.f;
        ov1[c] = erv[c + 4] + y;
    }
    float4* orow = reinterpret_cast<float4*>(e_out + (size_t)er * H_DIM + col0);
    __stcs(orow, o0);
    __stcs(orow + 1, o1);
}

// ---------------------------------------------------------------------------
// Kernel 3: node epilogue — g_agg holds Uh + bias + agg.
// ---------------------------------------------------------------------------
__global__ __launch_bounds__(256) void node_epilogue_kernel(
    const float* __restrict__ h,
    const float* __restrict__ gh, const float* __restrict__ bhv,
    float* __restrict__ h_out, int V)
{
    const int warp = threadIdx.x >> 5;
    const int lane = threadIdx.x & 31;
    const int n = blockIdx.x * 8 + warp;
    if (n >= V) return;
    const int col0 = lane * 8;

    const float4* ag = reinterpret_cast<const float4*>(g_agg + (size_t)n * H_DIM + col0);
    const float4* hr = reinterpret_cast<const float4*>(h     + (size_t)n * H_DIM + col0);

    float4 g0 = __ldcs(ag), g1 = __ldcs(ag + 1);
    float4 h0 = __ldcs(hr), h1 = __ldcs(hr + 1);

    float x[8], hv[8];
    x[0] = g0.x; x[1] = g0.y; x[2] = g0.z; x[3] = g0.w;
    x[4] = g1.x; x[5] = g1.y; x[6] = g1.z; x[7] = g1.w;
    hv[0] = h0.x; hv[1] = h0.y; hv[2] = h0.z; hv[3] = h0.w;
    hv[4] = h1.x; hv[5] = h1.y; hv[6] = h1.z; hv[7] = h1.w;

    float sum = 0.f, sq = 0.f;
    #pragma unroll
    for (int c = 0; c < 8; c++) { sum += x[c]; sq += x[c] * x[c]; }
    #pragma unroll
    for (int off = 16; off > 0; off >>= 1) {
        sum += __shfl_xor_sync(0xFFFFFFFFu, sum, off);
        sq  += __shfl_xor_sync(0xFFFFFFFFu, sq,  off);
    }
    const float mu  = sum * (1.f / 256.f);
    const float var = sq * (1.f / 256.f) - mu * mu;
    const float rs  = rsqrtf(var + LN_EPS);

    float4 o0, o1;
    float* ov0 = &o0.x; float* ov1 = &o1.x;
    #pragma unroll
    for (int c = 0; c < 4; c++) {
        float y = (x[c] - mu) * rs * gh[col0 + c] + bhv[col0 + c];
        y = y > 0.f ? y : 0.f;
        ov0[c] = hv[c] + y;
    }
    #pragma unroll
    for (int c = 0; c < 4; c++) {
        float y = (x[c + 4] - mu) * rs * gh[col0 + c + 4] + bhv[col0 + c + 4];
        y = y > 0.f ? y : 0.f;
        ov1[c] = hv[c + 4] + y;
    }
    float4* o = reinterpret_cast<float4*>(h_out + (size_t)n * H_DIM + col0);
    __stcs(o, o0);
    __stcs(o + 1, o1);
}

// ---------------------------------------------------------------------------
extern "C" void kernel_launch(void* const* d_in, const int* in_sizes, int n_in,
                              void* d_out, int out_size)
{
    const float* h  = (const float*)d_in[0];
    const float* e  = (const float*)d_in[1];
    const int*   ei = (const int*)  d_in[2];
    const float* Wu = (const float*)d_in[3];
    const float* bu = (const float*)d_in[4];
    const float* Wv = (const float*)d_in[5];
    const float* bv = (const float*)d_in[6];
    const float* Wa = (const float*)d_in[7];
    const float* ba = (const float*)d_in[8];
    const float* Wb = (const float*)d_in[9];
    const float* bb = (const float*)d_in[10];
    const float* Wc = (const float*)d_in[11];
    const float* bc = (const float*)d_in[12];
    const float* gh = (const float*)d_in[13];
    const float* bh = (const float*)d_in[14];
    const float* ge = (const float*)d_in[15];
    const float* be = (const float*)d_in[16];

    const int V = in_sizes[0] / H_DIM;
    const int E = in_sizes[1] / H_DIM;

    float* h_out = (float*)d_out;
    float* e_out = (float*)d_out + (size_t)V * H_DIM;

    static int attr_set = 0;
    if (!attr_set) {
        cudaFuncSetAttribute(node_gemm_persistent,
                             cudaFuncAttributeMaxDynamicSharedMemorySize, PG_SMEM_BYTES);
        cudaFuncSetAttribute(edge_gemm_kernel,
                             cudaFuncAttributeMaxDynamicSharedMemorySize, PG_SMEM_BYTES);
        attr_set = 1;
    }

    init_kernel<<<320, 256>>>(Wu, Wv, Wa, Wb, Wc);

    dim3 g1(8, 18);   // persistent per column-group, work-steal over row tiles
    node_gemm_persistent<<<g1, 512, PG_SMEM_BYTES>>>(h, bu, bv, ba, bb, V);

    dim3 g2(2, 74);   // persistent; work-steal over 625 tiles per half
    edge_gemm_kernel<<<g2, 512, PG_SMEM_BYTES>>>(e, E);

    edge_epilogue_kernel<<<E / 8, 256>>>(e, ei, bc, ge, be, e_out, E);

    node_epilogue_kernel<<<(V + 7) / 8, 256>>>(h, gh, bh, h_out, V);
}